// round 9
// baseline (speedup 1.0000x reference)
#include <cuda_runtime.h>
#include <cuda_fp16.h>
#include <cstdint>

#define BZ 4
#define DD 768
#define LL 4096
#define MM (BZ * LL)   // 16384
#define KW 2304        // split-K GEMM depth (3 x 768)
#define KA 1536        // compact A3 width: [Ah | Al]
#define NKC 72         // 2304 / 32 k-chunks
#define BKC 32
#define AS_STRIDE 40   // padded halfs per smem row
#define STAGE_BYTES (128 * AS_STRIDE * 2)  // 10240
#define NSTAGE 4
#define SM_TOTAL (NSTAGE * 2 * STAGE_BYTES)  // 81920

// Scratch (static device memory; no runtime alloc)
__device__ __align__(16) float g_u[MM * DD];        // U (fp32)
__device__ __align__(16) float g_p[MM * DD];        // P / Q (fp32)
__device__ __align__(16) float g_x3[MM * DD];       // X3 / B2-split (half MM x 1536) 48MB
__device__ __align__(16) float g_a3[MM * DD];       // relu(U)-split (half) OR enc (fp32) 48MB
__device__ __align__(16) __half g_wih3[DD * KW];    // W_ih split [Bh|Bl|Bh]
__device__ __align__(16) __half g_whh3[DD * KW];    // W_hh split

// ---------------------------------------------------------------------------
// PTX helpers (plain sm_80-era ISA: valid on virtual compute_103)
// ---------------------------------------------------------------------------
__device__ __forceinline__ uint32_t smem_u32(const void* p) {
    uint32_t a;
    asm("{ .reg .u64 t; cvta.to.shared.u64 t, %1; cvt.u32.u64 %0, t; }" : "=r"(a) : "l"(p));
    return a;
}
__device__ __forceinline__ void cp_async16(uint32_t saddr, const void* gaddr) {
    asm volatile("cp.async.cg.shared.global [%0], [%1], 16;" :: "r"(saddr), "l"(gaddr));
}
__device__ __forceinline__ void cp_commit() {
    asm volatile("cp.async.commit_group;");
}
__device__ __forceinline__ void cp_wait2() {
    asm volatile("cp.async.wait_group 2;");
}
__device__ __forceinline__ void ldm_x4(uint32_t& r0, uint32_t& r1, uint32_t& r2, uint32_t& r3,
                                       uint32_t addr) {
    asm volatile("ldmatrix.sync.aligned.m8n8.x4.shared.b16 {%0,%1,%2,%3}, [%4];"
                 : "=r"(r0), "=r"(r1), "=r"(r2), "=r"(r3) : "r"(addr));
}
__device__ __forceinline__ void mma16816(float* c, const uint32_t* a, const uint32_t* b) {
    asm volatile(
        "mma.sync.aligned.m16n8k16.row.col.f32.f16.f16.f32 "
        "{%0,%1,%2,%3}, {%4,%5,%6,%7}, {%8,%9}, {%0,%1,%2,%3};"
        : "+f"(c[0]), "+f"(c[1]), "+f"(c[2]), "+f"(c[3])
        : "r"(a[0]), "r"(a[1]), "r"(a[2]), "r"(a[3]), "r"(b[0]), "r"(b[1]));
}
__device__ __forceinline__ void split_h(float v, __half& h, __half& l) {
    h = __float2half_rn(v);
    l = __float2half_rn(v - __half2float(h));
}

// ---------------------------------------------------------------------------
// HMMA GEMM: C[M,768] = A3[M, split-K 2304] @ W3[768,2304]^T (+ bias1+bias2)
// BM=BN=128, BK=32, 4 warps (2x2), warp tile 64x64, 4-stage cp.async.
// k-chunk i source in compact A3: i<24 -> Ah, 24<=i<48 -> Ah, i>=48 -> Al.
// If SPLIT_OUT: also writes A3out = split(relu(C)) (compact [hi|lo] layout).
// ---------------------------------------------------------------------------
template <bool ADD_BIAS, bool SPLIT_OUT>
__global__ __launch_bounds__(128) void gemm_hmma(
    const __half* __restrict__ A3, const __half* __restrict__ B3,
    const float* __restrict__ bias1, const float* __restrict__ bias2,
    float* __restrict__ C, __half* __restrict__ A3out) {
    extern __shared__ __align__(16) unsigned char smem[];
    const uint32_t sa_base = smem_u32(smem);                       // A stages
    const uint32_t sb_base = sa_base + NSTAGE * STAGE_BYTES;       // B stages

    const int tid = threadIdx.x;
    const int wid = tid >> 5, lane = tid & 31;
    const int m0 = blockIdx.y * 128, n0 = blockIdx.x * 128;
    const int warp_m = (wid >> 1) * 64;   // 0,64
    const int warp_n = (wid & 1) * 64;    // 0,64

    // cp.async coords: thread handles rows cr+{0,32,64,96}, 16B-col cc
    const int cr = tid >> 2, cc = (tid & 3) * 8;

    float acc[4][8][4] = {};

    // ldmatrix per-lane address components
    const int a_row = warp_m + (lane & 7) + ((lane >> 3) & 1) * 8;  // + mt*16
    const int a_colh = (lane >> 4) * 8;                              // + ks*16
    const int b_row = warp_n + (lane & 7) + (lane >> 4) * 8;         // + j*16
    const int b_colh = ((lane >> 3) & 1) * 8;                        // + ks*16

    auto load_stage = [&](int chunk, int stage) {
        const int srcA = (chunk < 24) ? chunk * BKC
                       : (chunk < 48) ? (chunk - 24) * BKC
                                      : 768 + (chunk - 48) * BKC;
        const int kb = chunk * BKC;
        const uint32_t sa = sa_base + stage * STAGE_BYTES;
        const uint32_t sb = sb_base + stage * STAGE_BYTES;
        #pragma unroll
        for (int q = 0; q < 4; ++q) {
            const int r = cr + q * 32;
            cp_async16(sa + (r * AS_STRIDE + cc) * 2, A3 + (size_t)(m0 + r) * KA + srcA + cc);
            cp_async16(sb + (r * AS_STRIDE + cc) * 2, B3 + (size_t)(n0 + r) * KW + kb + cc);
        }
    };

    // prologue: stages 0,1,2
    load_stage(0, 0); cp_commit();
    load_stage(1, 1); cp_commit();
    load_stage(2, 2); cp_commit();

    for (int i = 0; i < NKC; ++i) {
        cp_wait2();
        __syncthreads();
        if (i + 3 < NKC) load_stage(i + 3, (i + 3) % NSTAGE);
        cp_commit();

        const int st = i % NSTAGE;
        const uint32_t a_st = sa_base + st * STAGE_BYTES;
        const uint32_t b_st = sb_base + st * STAGE_BYTES;

        #pragma unroll
        for (int ks = 0; ks < 2; ++ks) {
            uint32_t af[4][4], bf[8][2];
            #pragma unroll
            for (int mt = 0; mt < 4; ++mt)
                ldm_x4(af[mt][0], af[mt][1], af[mt][2], af[mt][3],
                       a_st + ((a_row + mt * 16) * AS_STRIDE + a_colh + ks * 16) * 2);
            #pragma unroll
            for (int j = 0; j < 4; ++j)
                ldm_x4(bf[2 * j][0], bf[2 * j][1], bf[2 * j + 1][0], bf[2 * j + 1][1],
                       b_st + ((b_row + j * 16) * AS_STRIDE + b_colh + ks * 16) * 2);
            #pragma unroll
            for (int mt = 0; mt < 4; ++mt)
                #pragma unroll
                for (int nt = 0; nt < 8; ++nt)
                    mma16816(acc[mt][nt], af[mt], bf[nt]);
        }
    }

    // epilogue
    #pragma unroll
    for (int mt = 0; mt < 4; ++mt) {
        #pragma unroll
        for (int h = 0; h < 2; ++h) {
            const int row = m0 + warp_m + mt * 16 + (lane >> 2) + h * 8;
            const int colb = n0 + warp_n + (lane & 3) * 2;
            float* cp = C + (size_t)row * DD + colb;
            #pragma unroll
            for (int nt = 0; nt < 8; ++nt) {
                float2 v;
                v.x = acc[mt][nt][h * 2 + 0];
                v.y = acc[mt][nt][h * 2 + 1];
                if (ADD_BIAS) {
                    const int n = colb + nt * 8;
                    v.x += bias1[n + 0] + bias2[n + 0];
                    v.y += bias1[n + 1] + bias2[n + 1];
                }
                *(float2*)(cp + nt * 8) = v;
                if (SPLIT_OUT) {
                    __half hh[2], ll[2];
                    split_h(fmaxf(v.x, 0.f), hh[0], ll[0]);
                    split_h(fmaxf(v.y, 0.f), hh[1], ll[1]);
                    __half* ao = A3out + (size_t)row * KA + colb + nt * 8;
                    *(uint32_t*)ao = *(const uint32_t*)hh;
                    *(uint32_t*)(ao + DD) = *(const uint32_t*)ll;
                }
            }
        }
    }
}

// ---------------------------------------------------------------------------
// Elementwise / prep kernels
// ---------------------------------------------------------------------------
// W [768,768] fp32 -> W3 [768,2304] = [Bh | Bl | Bh]
__global__ void conv_w_kernel(const float* __restrict__ W, __half* __restrict__ W3) {
    int idx = blockIdx.x * 256 + threadIdx.x;
    if (idx >= DD * DD) return;
    int r = idx / DD, k = idx % DD;
    __half h, l;
    split_h(W[idx], h, l);
    size_t base = (size_t)r * KW;
    W3[base + k] = h;
    W3[base + DD + k] = l;
    W3[base + 2 * DD + k] = h;
}

// x [B,D,L] fp32 -> X3 [B*L, 1536] half = [hi | lo] (transpose + split)
__global__ void conv_x_kernel(const float* __restrict__ x, __half* __restrict__ X3) {
    __shared__ float tile[32][33];
    int b = blockIdx.z, t0 = blockIdx.x * 32, d0 = blockIdx.y * 32;
    int tx = threadIdx.x;
    #pragma unroll
    for (int i = threadIdx.y; i < 32; i += 8)
        tile[tx][i] = x[(size_t)(b * DD + d0 + i) * LL + t0 + tx];
    __syncthreads();
    #pragma unroll
    for (int i = threadIdx.y; i < 32; i += 8) {
        __half h, l;
        split_h(tile[i][tx], h, l);
        size_t row = (size_t)(b * LL + t0 + i) * KA;
        X3[row + d0 + tx] = h;
        X3[row + DD + d0 + tx] = l;
    }
}

// A3 = split(relu(U + shift(P)))
__global__ void conv_shift_kernel(const float* __restrict__ U, const float* __restrict__ P,
                                  __half* __restrict__ A3) {
    int idx = blockIdx.x * 256 + threadIdx.x;
    int e = idx * 4;
    if (e >= MM * DD) return;
    int r = e / DD, c = e % DD;
    int t = r & (LL - 1);
    float4 u = *(const float4*)(U + e);
    float4 p = make_float4(0.f, 0.f, 0.f, 0.f);
    if (t > 0) p = *(const float4*)(P + e - DD);
    float v[4] = {fmaxf(u.x + p.x, 0.f), fmaxf(u.y + p.y, 0.f),
                  fmaxf(u.z + p.z, 0.f), fmaxf(u.w + p.w, 0.f)};
    __half h[4], l[4];
    #pragma unroll
    for (int j = 0; j < 4; ++j) split_h(v[j], h[j], l[j]);
    size_t base = (size_t)r * KA + c;
    *(uint2*)(A3 + base) = *(const uint2*)h;
    *(uint2*)(A3 + base + DD) = *(const uint2*)l;
}

// enc = transpose(relu(U + shift(Q))) -> [B, D, L] fp32
__global__ void c3_transpose_kernel(const float* __restrict__ U, const float* __restrict__ Q,
                                    float* __restrict__ enc) {
    __shared__ float tile[32][33];
    int b = blockIdx.z, t0 = blockIdx.x * 32, d0 = blockIdx.y * 32;
    int tx = threadIdx.x;
    #pragma unroll
    for (int i = threadIdx.y; i < 32; i += 8) {
        int t = t0 + i;
        int r = b * LL + t;
        float u = U[(size_t)r * DD + d0 + tx];
        float q = (t > 0) ? Q[(size_t)(r - 1) * DD + d0 + tx] : 0.f;
        tile[i][tx] = fmaxf(u + q, 0.f);
    }
    __syncthreads();
    #pragma unroll
    for (int i = threadIdx.y; i < 32; i += 8)
        enc[(size_t)(b * DD + d0 + i) * LL + t0 + tx] = tile[tx][i];
}

// LayerNorm over L per (b,d) row
__global__ __launch_bounds__(256) void layernorm_kernel(
    const float* __restrict__ enc, const float* __restrict__ x,
    const float* __restrict__ gamma, const float* __restrict__ beta,
    float* __restrict__ out) {
    __shared__ float zbuf[LL];
    __shared__ float red[256];
    int row = blockIdx.x;
    int tid = threadIdx.x;
    const float* e = enc + (size_t)row * LL;
    const float* xx = x + (size_t)row * LL;
    float* op = out + (size_t)row * LL;

    float s = 0.f;
    for (int t = tid; t < LL; t += 256) {
        float z = e[t] + xx[t];
        zbuf[t] = z;
        s += z;
    }
    red[tid] = s;
    __syncthreads();
    #pragma unroll
    for (int o = 128; o > 0; o >>= 1) {
        if (tid < o) red[tid] += red[tid + o];
        __syncthreads();
    }
    float mean = red[0] * (1.f / LL);
    __syncthreads();

    float v = 0.f;
    for (int t = tid; t < LL; t += 256) {
        float d = zbuf[t] - mean;
        v += d * d;
    }
    red[tid] = v;
    __syncthreads();
    #pragma unroll
    for (int o = 128; o > 0; o >>= 1) {
        if (tid < o) red[tid] += red[tid + o];
        __syncthreads();
    }
    float rstd = rsqrtf(red[0] * (1.f / LL) + 1e-12f);

    for (int t = tid; t < LL; t += 256)
        op[t] = (zbuf[t] - mean) * rstd * gamma[t] + beta[t];
}

// ---------------------------------------------------------------------------
// Launch
// ---------------------------------------------------------------------------
extern "C" void kernel_launch(void* const* d_in, const int* in_sizes, int n_in,
                              void* d_out, int out_size) {
    const float* x = (const float*)d_in[0];
    const float* W_ih = (const float*)d_in[1];
    const float* W_hh = (const float*)d_in[2];
    const float* b_ih = (const float*)d_in[3];
    const float* b_hh = (const float*)d_in[4];
    const float* gamma = (const float*)d_in[5];
    const float* beta = (const float*)d_in[6];
    float* out = (float*)d_out;

    float *pu, *pp, *px3, *pa3;
    __half *pwih3, *pwhh3;
    cudaGetSymbolAddress((void**)&pu, g_u);
    cudaGetSymbolAddress((void**)&pp, g_p);
    cudaGetSymbolAddress((void**)&px3, g_x3);
    cudaGetSymbolAddress((void**)&pa3, g_a3);
    cudaGetSymbolAddress((void**)&pwih3, g_wih3);
    cudaGetSymbolAddress((void**)&pwhh3, g_whh3);
    __half* hx3 = (__half*)px3;   // X3 input, later B2 split
    __half* ha3 = (__half*)pa3;   // relu(U) split; later enc (fp32)

    cudaFuncSetAttribute(gemm_hmma<true, true>, cudaFuncAttributeMaxDynamicSharedMemorySize, SM_TOTAL);
    cudaFuncSetAttribute(gemm_hmma<false, false>, cudaFuncAttributeMaxDynamicSharedMemorySize, SM_TOTAL);

    dim3 tgrid(LL / 32, DD / 32, BZ), tblk(32, 8);
    dim3 ggrid(DD / 128, MM / 128);  // (6, 128)
    const int ew_blocks = (MM * DD / 4 + 255) / 256;

    // W splits
    conv_w_kernel<<<(DD * DD + 255) / 256, 256>>>(W_ih, pwih3);
    conv_w_kernel<<<(DD * DD + 255) / 256, 256>>>(W_hh, pwhh3);
    // X3 = split(transpose(x))
    conv_x_kernel<<<tgrid, tblk>>>(x, hx3);
    // U = X @ W_ih^T + b_ih + b_hh ; fused: A3relu = split(relu(U))
    gemm_hmma<true, true><<<ggrid, 128, SM_TOTAL>>>(hx3, pwih3, b_ih, b_hh, pu, ha3);
    // P = relu(U) @ W_hh^T
    gemm_hmma<false, false><<<ggrid, 128, SM_TOTAL>>>(ha3, pwhh3, nullptr, nullptr, pp, nullptr);
    // B2split = split(relu(U + shift(P)))  -> g_x3 (X3 no longer needed)
    conv_shift_kernel<<<ew_blocks, 256>>>(pu, pp, hx3);
    // Q = B2 @ W_hh^T
    gemm_hmma<false, false><<<ggrid, 128, SM_TOTAL>>>(hx3, pwhh3, nullptr, nullptr, pp, nullptr);
    // enc = transpose(relu(U + shift(Q)))  -> g_a3 as fp32
    c3_transpose_kernel<<<tgrid, tblk>>>(pu, pp, pa3);
    // out = LayerNorm_L(enc + x)
    layernorm_kernel<<<BZ * DD, 256>>>(pa3, x, gamma, beta, out);
}

// round 10
// speedup vs baseline: 1.1710x; 1.1710x over previous
#include <cuda_runtime.h>
#include <cuda_fp16.h>
#include <cstdint>

#define BZ 4
#define DD 768
#define LL 4096
#define MM (BZ * LL)   // 16384
#define KW 2304        // split-K GEMM depth (3 x 768)
#define KA 1536        // compact A3 width: [Ah | Al]
#define BKC 64
#define NKC 36         // 2304 / 64 k-chunks
#define AS_STRIDE 72   // padded halfs per smem row (144B, ldmatrix conflict-free)
#define STAGE_BYTES (128 * AS_STRIDE * 2)  // 18432
#define NSTAGE 3
#define SM_TOTAL (NSTAGE * 2 * STAGE_BYTES)  // 110592

// Scratch (static device memory; no runtime alloc)
__device__ __align__(16) float g_u[MM * DD];        // U (fp32)
__device__ __align__(16) float g_p[MM * DD];        // P / Q (fp32)
__device__ __align__(16) float g_x3[MM * DD];       // X3 split, later B2 split (half MM x 1536)
__device__ __align__(16) float g_a3[MM * DD];       // relu(U) split (half), later enc (fp32)
__device__ __align__(16) __half g_wih3[DD * KW];    // W_ih split [Bh|Bl|Bh]
__device__ __align__(16) __half g_whh3[DD * KW];    // W_hh split

// ---------------------------------------------------------------------------
// PTX helpers (plain sm_80-era ISA: valid on virtual compute_103)
// ---------------------------------------------------------------------------
__device__ __forceinline__ uint32_t smem_u32(const void* p) {
    uint32_t a;
    asm("{ .reg .u64 t; cvta.to.shared.u64 t, %1; cvt.u32.u64 %0, t; }" : "=r"(a) : "l"(p));
    return a;
}
__device__ __forceinline__ void cp_async16(uint32_t saddr, const void* gaddr) {
    asm volatile("cp.async.cg.shared.global [%0], [%1], 16;" :: "r"(saddr), "l"(gaddr));
}
__device__ __forceinline__ void cp_commit() {
    asm volatile("cp.async.commit_group;");
}
__device__ __forceinline__ void cp_wait1() {
    asm volatile("cp.async.wait_group 1;");
}
__device__ __forceinline__ void ldm_x4(uint32_t& r0, uint32_t& r1, uint32_t& r2, uint32_t& r3,
                                       uint32_t addr) {
    asm volatile("ldmatrix.sync.aligned.m8n8.x4.shared.b16 {%0,%1,%2,%3}, [%4];"
                 : "=r"(r0), "=r"(r1), "=r"(r2), "=r"(r3) : "r"(addr));
}
__device__ __forceinline__ void mma16816(float* c, const uint32_t* a, const uint32_t* b) {
    asm volatile(
        "mma.sync.aligned.m16n8k16.row.col.f32.f16.f16.f32 "
        "{%0,%1,%2,%3}, {%4,%5,%6,%7}, {%8,%9}, {%0,%1,%2,%3};"
        : "+f"(c[0]), "+f"(c[1]), "+f"(c[2]), "+f"(c[3])
        : "r"(a[0]), "r"(a[1]), "r"(a[2]), "r"(a[3]), "r"(b[0]), "r"(b[1]));
}
__device__ __forceinline__ void split_h(float v, __half& h, __half& l) {
    h = __float2half_rn(v);
    l = __float2half_rn(v - __half2float(h));
}

// ---------------------------------------------------------------------------
// HMMA GEMM: C[M,768] = A3[M, split-K 2304] @ W3[768,2304]^T (+ bias1+bias2)
// BM=BN=128, BK=64, 8 warps (4x2), warp tile 32x64, 3-stage cp.async.
// k-chunk i (of 36) source in compact A3: i<12 -> Ah, 12<=i<24 -> Ah, i>=24 -> Al.
// If SPLIT_OUT: also writes A3out = split(relu(C)) (compact [hi|lo] layout).
// ---------------------------------------------------------------------------
template <bool ADD_BIAS, bool SPLIT_OUT>
__global__ __launch_bounds__(256, 2) void gemm_hmma(
    const __half* __restrict__ A3, const __half* __restrict__ B3,
    const float* __restrict__ bias1, const float* __restrict__ bias2,
    float* __restrict__ C, __half* __restrict__ A3out) {
    extern __shared__ __align__(16) unsigned char smem[];
    const uint32_t sa_base = smem_u32(smem);                       // A stages
    const uint32_t sb_base = sa_base + NSTAGE * STAGE_BYTES;       // B stages

    const int tid = threadIdx.x;
    const int wid = tid >> 5, lane = tid & 31;
    const int m0 = blockIdx.y * 128, n0 = blockIdx.x * 128;
    const int warp_m = (wid >> 1) * 32;   // 0,32,64,96
    const int warp_n = (wid & 1) * 64;    // 0,64

    // cp.async coords: 1024 16B-chunks per operand per stage; 4 per thread.
    const int cr = tid >> 3;          // row base 0..31 (+q*32)
    const int cc = (tid & 7) * 8;     // half col 0..56

    float acc[2][8][4] = {};

    // ldmatrix per-lane address components
    const int a_row = warp_m + (lane & 7) + ((lane >> 3) & 1) * 8;  // + mt*16
    const int a_colh = (lane >> 4) * 8;                              // + ks*16
    const int b_row = warp_n + (lane & 7) + (lane >> 4) * 8;         // + j*16
    const int b_colh = ((lane >> 3) & 1) * 8;                        // + ks*16

    auto load_stage = [&](int chunk, int stage) {
        const int srcA = (chunk < 12) ? chunk * BKC
                       : (chunk < 24) ? (chunk - 12) * BKC
                                      : 768 + (chunk - 24) * BKC;
        const int kb = chunk * BKC;
        const uint32_t sa = sa_base + stage * STAGE_BYTES;
        const uint32_t sb = sb_base + stage * STAGE_BYTES;
        #pragma unroll
        for (int q = 0; q < 4; ++q) {
            const int r = cr + q * 32;
            cp_async16(sa + (r * AS_STRIDE + cc) * 2, A3 + (size_t)(m0 + r) * KA + srcA + cc);
            cp_async16(sb + (r * AS_STRIDE + cc) * 2, B3 + (size_t)(n0 + r) * KW + kb + cc);
        }
    };

    // prologue: stages 0,1
    load_stage(0, 0); cp_commit();
    load_stage(1, 1); cp_commit();

    for (int i = 0; i < NKC; ++i) {
        cp_wait1();
        __syncthreads();
        if (i + 2 < NKC) load_stage(i + 2, (i + 2) % NSTAGE);
        cp_commit();

        const int st = i % NSTAGE;
        const uint32_t a_st = sa_base + st * STAGE_BYTES;
        const uint32_t b_st = sb_base + st * STAGE_BYTES;

        #pragma unroll
        for (int ks = 0; ks < 4; ++ks) {
            uint32_t af[2][4], bf[8][2];
            #pragma unroll
            for (int mt = 0; mt < 2; ++mt)
                ldm_x4(af[mt][0], af[mt][1], af[mt][2], af[mt][3],
                       a_st + ((a_row + mt * 16) * AS_STRIDE + a_colh + ks * 16) * 2);
            #pragma unroll
            for (int j = 0; j < 4; ++j)
                ldm_x4(bf[2 * j][0], bf[2 * j][1], bf[2 * j + 1][0], bf[2 * j + 1][1],
                       b_st + ((b_row + j * 16) * AS_STRIDE + b_colh + ks * 16) * 2);
            #pragma unroll
            for (int mt = 0; mt < 2; ++mt)
                #pragma unroll
                for (int nt = 0; nt < 8; ++nt)
                    mma16816(acc[mt][nt], af[mt], bf[nt]);
        }
    }

    // epilogue
    #pragma unroll
    for (int mt = 0; mt < 2; ++mt) {
        #pragma unroll
        for (int h = 0; h < 2; ++h) {
            const int row = m0 + warp_m + mt * 16 + (lane >> 2) + h * 8;
            const int colb = n0 + warp_n + (lane & 3) * 2;
            float* cp = C + (size_t)row * DD + colb;
            #pragma unroll
            for (int nt = 0; nt < 8; ++nt) {
                float2 v;
                v.x = acc[mt][nt][h * 2 + 0];
                v.y = acc[mt][nt][h * 2 + 1];
                if (ADD_BIAS) {
                    const int n = colb + nt * 8;
                    v.x += bias1[n + 0] + bias2[n + 0];
                    v.y += bias1[n + 1] + bias2[n + 1];
                }
                *(float2*)(cp + nt * 8) = v;
                if (SPLIT_OUT) {
                    __half hh[2], ll[2];
                    split_h(fmaxf(v.x, 0.f), hh[0], ll[0]);
                    split_h(fmaxf(v.y, 0.f), hh[1], ll[1]);
                    __half* ao = A3out + (size_t)row * KA + colb + nt * 8;
                    *(uint32_t*)ao = *(const uint32_t*)hh;
                    *(uint32_t*)(ao + DD) = *(const uint32_t*)ll;
                }
            }
        }
    }
}

// ---------------------------------------------------------------------------
// Elementwise / prep kernels
// ---------------------------------------------------------------------------
// W [768,768] fp32 -> W3 [768,2304] = [Bh | Bl | Bh]
__global__ void conv_w_kernel(const float* __restrict__ W, __half* __restrict__ W3) {
    int idx = blockIdx.x * 256 + threadIdx.x;
    if (idx >= DD * DD) return;
    int r = idx / DD, k = idx % DD;
    __half h, l;
    split_h(W[idx], h, l);
    size_t base = (size_t)r * KW;
    W3[base + k] = h;
    W3[base + DD + k] = l;
    W3[base + 2 * DD + k] = h;
}

// x [B,D,L] fp32 -> X3 [B*L, 1536] half = [hi | lo] (transpose + split)
__global__ void conv_x_kernel(const float* __restrict__ x, __half* __restrict__ X3) {
    __shared__ float tile[32][33];
    int b = blockIdx.z, t0 = blockIdx.x * 32, d0 = blockIdx.y * 32;
    int tx = threadIdx.x;
    #pragma unroll
    for (int i = threadIdx.y; i < 32; i += 8)
        tile[tx][i] = x[(size_t)(b * DD + d0 + i) * LL + t0 + tx];
    __syncthreads();
    #pragma unroll
    for (int i = threadIdx.y; i < 32; i += 8) {
        __half h, l;
        split_h(tile[i][tx], h, l);
        size_t row = (size_t)(b * LL + t0 + i) * KA;
        X3[row + d0 + tx] = h;
        X3[row + DD + d0 + tx] = l;
    }
}

// A3 = split(relu(U + shift(P)))
__global__ void conv_shift_kernel(const float* __restrict__ U, const float* __restrict__ P,
                                  __half* __restrict__ A3) {
    int idx = blockIdx.x * 256 + threadIdx.x;
    int e = idx * 4;
    if (e >= MM * DD) return;
    int r = e / DD, c = e % DD;
    int t = r & (LL - 1);
    float4 u = *(const float4*)(U + e);
    float4 p = make_float4(0.f, 0.f, 0.f, 0.f);
    if (t > 0) p = *(const float4*)(P + e - DD);
    float v[4] = {fmaxf(u.x + p.x, 0.f), fmaxf(u.y + p.y, 0.f),
                  fmaxf(u.z + p.z, 0.f), fmaxf(u.w + p.w, 0.f)};
    __half h[4], l[4];
    #pragma unroll
    for (int j = 0; j < 4; ++j) split_h(v[j], h[j], l[j]);
    size_t base = (size_t)r * KA + c;
    *(uint2*)(A3 + base) = *(const uint2*)h;
    *(uint2*)(A3 + base + DD) = *(const uint2*)l;
}

// enc = transpose(relu(U + shift(Q))) -> [B, D, L] fp32
__global__ void c3_transpose_kernel(const float* __restrict__ U, const float* __restrict__ Q,
                                    float* __restrict__ enc) {
    __shared__ float tile[32][33];
    int b = blockIdx.z, t0 = blockIdx.x * 32, d0 = blockIdx.y * 32;
    int tx = threadIdx.x;
    #pragma unroll
    for (int i = threadIdx.y; i < 32; i += 8) {
        int t = t0 + i;
        int r = b * LL + t;
        float u = U[(size_t)r * DD + d0 + tx];
        float q = (t > 0) ? Q[(size_t)(r - 1) * DD + d0 + tx] : 0.f;
        tile[i][tx] = fmaxf(u + q, 0.f);
    }
    __syncthreads();
    #pragma unroll
    for (int i = threadIdx.y; i < 32; i += 8)
        enc[(size_t)(b * DD + d0 + i) * LL + t0 + tx] = tile[tx][i];
}

// LayerNorm over L per (b,d) row
__global__ __launch_bounds__(256) void layernorm_kernel(
    const float* __restrict__ enc, const float* __restrict__ x,
    const float* __restrict__ gamma, const float* __restrict__ beta,
    float* __restrict__ out) {
    __shared__ float zbuf[LL];
    __shared__ float red[256];
    int row = blockIdx.x;
    int tid = threadIdx.x;
    const float* e = enc + (size_t)row * LL;
    const float* xx = x + (size_t)row * LL;
    float* op = out + (size_t)row * LL;

    float s = 0.f;
    for (int t = tid; t < LL; t += 256) {
        float z = e[t] + xx[t];
        zbuf[t] = z;
        s += z;
    }
    red[tid] = s;
    __syncthreads();
    #pragma unroll
    for (int o = 128; o > 0; o >>= 1) {
        if (tid < o) red[tid] += red[tid + o];
        __syncthreads();
    }
    float mean = red[0] * (1.f / LL);
    __syncthreads();

    float v = 0.f;
    for (int t = tid; t < LL; t += 256) {
        float d = zbuf[t] - mean;
        v += d * d;
    }
    red[tid] = v;
    __syncthreads();
    #pragma unroll
    for (int o = 128; o > 0; o >>= 1) {
        if (tid < o) red[tid] += red[tid + o];
        __syncthreads();
    }
    float rstd = rsqrtf(red[0] * (1.f / LL) + 1e-12f);

    for (int t = tid; t < LL; t += 256)
        op[t] = (zbuf[t] - mean) * rstd * gamma[t] + beta[t];
}

// ---------------------------------------------------------------------------
// Launch
// ---------------------------------------------------------------------------
extern "C" void kernel_launch(void* const* d_in, const int* in_sizes, int n_in,
                              void* d_out, int out_size) {
    const float* x = (const float*)d_in[0];
    const float* W_ih = (const float*)d_in[1];
    const float* W_hh = (const float*)d_in[2];
    const float* b_ih = (const float*)d_in[3];
    const float* b_hh = (const float*)d_in[4];
    const float* gamma = (const float*)d_in[5];
    const float* beta = (const float*)d_in[6];
    float* out = (float*)d_out;

    float *pu, *pp, *px3, *pa3;
    __half *pwih3, *pwhh3;
    cudaGetSymbolAddress((void**)&pu, g_u);
    cudaGetSymbolAddress((void**)&pp, g_p);
    cudaGetSymbolAddress((void**)&px3, g_x3);
    cudaGetSymbolAddress((void**)&pa3, g_a3);
    cudaGetSymbolAddress((void**)&pwih3, g_wih3);
    cudaGetSymbolAddress((void**)&pwhh3, g_whh3);
    __half* hx3 = (__half*)px3;   // X3 input, later B2 split
    __half* ha3 = (__half*)pa3;   // relu(U) split; later enc (fp32)

    cudaFuncSetAttribute(gemm_hmma<true, true>, cudaFuncAttributeMaxDynamicSharedMemorySize, SM_TOTAL);
    cudaFuncSetAttribute(gemm_hmma<false, false>, cudaFuncAttributeMaxDynamicSharedMemorySize, SM_TOTAL);

    dim3 tgrid(LL / 32, DD / 32, BZ), tblk(32, 8);
    dim3 ggrid(DD / 128, MM / 128);  // (6, 128)
    const int ew_blocks = (MM * DD / 4 + 255) / 256;

    // W splits
    conv_w_kernel<<<(DD * DD + 255) / 256, 256>>>(W_ih, pwih3);
    conv_w_kernel<<<(DD * DD + 255) / 256, 256>>>(W_hh, pwhh3);
    // X3 = split(transpose(x))
    conv_x_kernel<<<tgrid, tblk>>>(x, hx3);
    // U = X @ W_ih^T + b_ih + b_hh ; fused: A3relu = split(relu(U))
    gemm_hmma<true, true><<<ggrid, 256, SM_TOTAL>>>(hx3, pwih3, b_ih, b_hh, pu, ha3);
    // P = relu(U) @ W_hh^T
    gemm_hmma<false, false><<<ggrid, 256, SM_TOTAL>>>(ha3, pwhh3, nullptr, nullptr, pp, nullptr);
    // B2split = split(relu(U + shift(P)))  -> g_x3 (X3 dead after GEMM1)
    conv_shift_kernel<<<ew_blocks, 256>>>(pu, pp, hx3);
    // Q = B2 @ W_hh^T
    gemm_hmma<false, false><<<ggrid, 256, SM_TOTAL>>>(hx3, pwhh3, nullptr, nullptr, pp, nullptr);
    // enc = transpose(relu(U + shift(Q)))  -> g_a3 as fp32
    c3_transpose_kernel<<<tgrid, tblk>>>(pu, pp, pa3);
    // out = LayerNorm_L(enc + x)
    layernorm_kernel<<<BZ * DD, 256>>>(pa3, x, gamma, beta, out);
}

// round 11
// speedup vs baseline: 1.5448x; 1.3191x over previous
#include <cuda_runtime.h>
#include <cuda_fp16.h>
#include <cstdint>

#define BZ 4
#define DD 768
#define LL 4096
#define MM (BZ * LL)   // 16384
#define KA 1536        // compact A3 width: [Ah | Al]  (= GEMM K)
#define BKC 64
#define NKC 24         // 1536 / 64 k-chunks
#define AS_STRIDE 72   // padded halfs per smem row (144B, ldmatrix conflict-free)
#define STAGE_BYTES (128 * AS_STRIDE * 2)  // 18432
#define NSTAGE 3
#define SM_TOTAL (NSTAGE * 2 * STAGE_BYTES)  // 110592

// Scratch (static device memory; no runtime alloc)
__device__ __align__(16) float g_u[MM * DD];        // U (fp32)
__device__ __align__(16) float g_p[MM * DD];        // P / Q (fp32)
__device__ __align__(16) float g_x3[MM * DD];       // X3 split, later B2 split (half MM x 1536)
__device__ __align__(16) float g_a3[MM * DD];       // relu(U) split (half), later enc (fp32)
__device__ __align__(16) __half g_wih[DD * DD];     // W_ih high half
__device__ __align__(16) __half g_whh[DD * DD];     // W_hh high half

// ---------------------------------------------------------------------------
// PTX helpers (plain sm_80-era ISA: valid on virtual compute_103)
// ---------------------------------------------------------------------------
__device__ __forceinline__ uint32_t smem_u32(const void* p) {
    uint32_t a;
    asm("{ .reg .u64 t; cvta.to.shared.u64 t, %1; cvt.u32.u64 %0, t; }" : "=r"(a) : "l"(p));
    return a;
}
__device__ __forceinline__ void cp_async16(uint32_t saddr, const void* gaddr) {
    asm volatile("cp.async.cg.shared.global [%0], [%1], 16;" :: "r"(saddr), "l"(gaddr));
}
__device__ __forceinline__ void cp_commit() {
    asm volatile("cp.async.commit_group;");
}
__device__ __forceinline__ void cp_wait1() {
    asm volatile("cp.async.wait_group 1;");
}
__device__ __forceinline__ void ldm_x4(uint32_t& r0, uint32_t& r1, uint32_t& r2, uint32_t& r3,
                                       uint32_t addr) {
    asm volatile("ldmatrix.sync.aligned.m8n8.x4.shared.b16 {%0,%1,%2,%3}, [%4];"
                 : "=r"(r0), "=r"(r1), "=r"(r2), "=r"(r3) : "r"(addr));
}
__device__ __forceinline__ void mma16816(float* c, const uint32_t* a, const uint32_t* b) {
    asm volatile(
        "mma.sync.aligned.m16n8k16.row.col.f32.f16.f16.f32 "
        "{%0,%1,%2,%3}, {%4,%5,%6,%7}, {%8,%9}, {%0,%1,%2,%3};"
        : "+f"(c[0]), "+f"(c[1]), "+f"(c[2]), "+f"(c[3])
        : "r"(a[0]), "r"(a[1]), "r"(a[2]), "r"(a[3]), "r"(b[0]), "r"(b[1]));
}
__device__ __forceinline__ void split_h(float v, __half& h, __half& l) {
    h = __float2half_rn(v);
    l = __float2half_rn(v - __half2float(h));
}

// ---------------------------------------------------------------------------
// HMMA GEMM: C[M,768] = (Ah+Al)[M,1536-compact] @ Wh[768,768]^T (+ bias1+bias2)
// 2-term split: chunks 0-11 feed Ah x Bh, chunks 12-23 feed Al x Bh.
// BM=BN=128, BK=64, 8 warps (4x2), warp tile 32x64, 3-stage cp.async.
// If SPLIT_OUT: also writes A3out = split(relu(C)) (compact [hi|lo] layout).
// ---------------------------------------------------------------------------
template <bool ADD_BIAS, bool SPLIT_OUT>
__global__ __launch_bounds__(256, 2) void gemm_hmma(
    const __half* __restrict__ A3, const __half* __restrict__ Bh,
    const float* __restrict__ bias1, const float* __restrict__ bias2,
    float* __restrict__ C, __half* __restrict__ A3out) {
    extern __shared__ __align__(16) unsigned char smem[];
    const uint32_t sa_base = smem_u32(smem);                       // A stages
    const uint32_t sb_base = sa_base + NSTAGE * STAGE_BYTES;       // B stages

    const int tid = threadIdx.x;
    const int wid = tid >> 5, lane = tid & 31;
    const int m0 = blockIdx.y * 128, n0 = blockIdx.x * 128;
    const int warp_m = (wid >> 1) * 32;   // 0,32,64,96
    const int warp_n = (wid & 1) * 64;    // 0,64

    // cp.async coords: 1024 16B-chunks per operand per stage; 4 per thread.
    const int cr = tid >> 3;          // row base 0..31 (+q*32)
    const int cc = (tid & 7) * 8;     // half col 0..56

    float acc[2][8][4] = {};

    // ldmatrix per-lane address components
    const int a_row = warp_m + (lane & 7) + ((lane >> 3) & 1) * 8;  // + mt*16
    const int a_colh = (lane >> 4) * 8;                              // + ks*16
    const int b_row = warp_n + (lane & 7) + (lane >> 4) * 8;         // + j*16
    const int b_colh = ((lane >> 3) & 1) * 8;                        // + ks*16

    auto load_stage = [&](int chunk, int stage) {
        const int srcA = chunk * BKC;                                  // sequential in [Ah|Al]
        const int kb = (chunk < 12 ? chunk : chunk - 12) * BKC;        // Bh reused for both terms
        const uint32_t sa = sa_base + stage * STAGE_BYTES;
        const uint32_t sb = sb_base + stage * STAGE_BYTES;
        #pragma unroll
        for (int q = 0; q < 4; ++q) {
            const int r = cr + q * 32;
            cp_async16(sa + (r * AS_STRIDE + cc) * 2, A3 + (size_t)(m0 + r) * KA + srcA + cc);
            cp_async16(sb + (r * AS_STRIDE + cc) * 2, Bh + (size_t)(n0 + r) * DD + kb + cc);
        }
    };

    // prologue: stages 0,1
    load_stage(0, 0); cp_commit();
    load_stage(1, 1); cp_commit();

    for (int i = 0; i < NKC; ++i) {
        cp_wait1();
        __syncthreads();
        if (i + 2 < NKC) load_stage(i + 2, (i + 2) % NSTAGE);
        cp_commit();

        const int st = i % NSTAGE;
        const uint32_t a_st = sa_base + st * STAGE_BYTES;
        const uint32_t b_st = sb_base + st * STAGE_BYTES;

        #pragma unroll
        for (int ks = 0; ks < 4; ++ks) {
            uint32_t af[2][4], bf[8][2];
            #pragma unroll
            for (int mt = 0; mt < 2; ++mt)
                ldm_x4(af[mt][0], af[mt][1], af[mt][2], af[mt][3],
                       a_st + ((a_row + mt * 16) * AS_STRIDE + a_colh + ks * 16) * 2);
            #pragma unroll
            for (int j = 0; j < 4; ++j)
                ldm_x4(bf[2 * j][0], bf[2 * j][1], bf[2 * j + 1][0], bf[2 * j + 1][1],
                       b_st + ((b_row + j * 16) * AS_STRIDE + b_colh + ks * 16) * 2);
            #pragma unroll
            for (int mt = 0; mt < 2; ++mt)
                #pragma unroll
                for (int nt = 0; nt < 8; ++nt)
                    mma16816(acc[mt][nt], af[mt], bf[nt]);
        }
    }

    // epilogue
    #pragma unroll
    for (int mt = 0; mt < 2; ++mt) {
        #pragma unroll
        for (int h = 0; h < 2; ++h) {
            const int row = m0 + warp_m + mt * 16 + (lane >> 2) + h * 8;
            const int colb = n0 + warp_n + (lane & 3) * 2;
            float* cp = C + (size_t)row * DD + colb;
            #pragma unroll
            for (int nt = 0; nt < 8; ++nt) {
                float2 v;
                v.x = acc[mt][nt][h * 2 + 0];
                v.y = acc[mt][nt][h * 2 + 1];
                if (ADD_BIAS) {
                    const int n = colb + nt * 8;
                    v.x += bias1[n + 0] + bias2[n + 0];
                    v.y += bias1[n + 1] + bias2[n + 1];
                }
                *(float2*)(cp + nt * 8) = v;
                if (SPLIT_OUT) {
                    __half hh[2], ll[2];
                    split_h(fmaxf(v.x, 0.f), hh[0], ll[0]);
                    split_h(fmaxf(v.y, 0.f), hh[1], ll[1]);
                    __half* ao = A3out + (size_t)row * KA + colb + nt * 8;
                    *(uint32_t*)ao = *(const uint32_t*)hh;
                    *(uint32_t*)(ao + DD) = *(const uint32_t*)ll;
                }
            }
        }
    }
}

// ---------------------------------------------------------------------------
// Elementwise / prep kernels
// ---------------------------------------------------------------------------
// W [768,768] fp32 -> Wh [768,768] half (high part only)
__global__ void conv_w_kernel(const float* __restrict__ W, __half* __restrict__ Wh) {
    int idx = blockIdx.x * 256 + threadIdx.x;
    if (idx >= DD * DD) return;
    Wh[idx] = __float2half_rn(W[idx]);
}

// x [B,D,L] fp32 -> X3 [B*L, 1536] half = [hi | lo] (transpose + split)
__global__ void conv_x_kernel(const float* __restrict__ x, __half* __restrict__ X3) {
    __shared__ float tile[32][33];
    int b = blockIdx.z, t0 = blockIdx.x * 32, d0 = blockIdx.y * 32;
    int tx = threadIdx.x;
    #pragma unroll
    for (int i = threadIdx.y; i < 32; i += 8)
        tile[tx][i] = x[(size_t)(b * DD + d0 + i) * LL + t0 + tx];
    __syncthreads();
    #pragma unroll
    for (int i = threadIdx.y; i < 32; i += 8) {
        __half h, l;
        split_h(tile[i][tx], h, l);
        size_t row = (size_t)(b * LL + t0 + i) * KA;
        X3[row + d0 + tx] = h;
        X3[row + DD + d0 + tx] = l;
    }
}

// A3 = split(relu(U + shift(P)))
__global__ void conv_shift_kernel(const float* __restrict__ U, const float* __restrict__ P,
                                  __half* __restrict__ A3) {
    int idx = blockIdx.x * 256 + threadIdx.x;
    int e = idx * 4;
    if (e >= MM * DD) return;
    int r = e / DD, c = e % DD;
    int t = r & (LL - 1);
    float4 u = *(const float4*)(U + e);
    float4 p = make_float4(0.f, 0.f, 0.f, 0.f);
    if (t > 0) p = *(const float4*)(P + e - DD);
    float v[4] = {fmaxf(u.x + p.x, 0.f), fmaxf(u.y + p.y, 0.f),
                  fmaxf(u.z + p.z, 0.f), fmaxf(u.w + p.w, 0.f)};
    __half h[4], l[4];
    #pragma unroll
    for (int j = 0; j < 4; ++j) split_h(v[j], h[j], l[j]);
    size_t base = (size_t)r * KA + c;
    *(uint2*)(A3 + base) = *(const uint2*)h;
    *(uint2*)(A3 + base + DD) = *(const uint2*)l;
}

// enc = transpose(relu(U + shift(Q))) -> [B, D, L] fp32
__global__ void c3_transpose_kernel(const float* __restrict__ U, const float* __restrict__ Q,
                                    float* __restrict__ enc) {
    __shared__ float tile[32][33];
    int b = blockIdx.z, t0 = blockIdx.x * 32, d0 = blockIdx.y * 32;
    int tx = threadIdx.x;
    #pragma unroll
    for (int i = threadIdx.y; i < 32; i += 8) {
        int t = t0 + i;
        int r = b * LL + t;
        float u = U[(size_t)r * DD + d0 + tx];
        float q = (t > 0) ? Q[(size_t)(r - 1) * DD + d0 + tx] : 0.f;
        tile[i][tx] = fmaxf(u + q, 0.f);
    }
    __syncthreads();
    #pragma unroll
    for (int i = threadIdx.y; i < 32; i += 8)
        enc[(size_t)(b * DD + d0 + i) * LL + t0 + tx] = tile[tx][i];
}

// LayerNorm over L per (b,d) row
__global__ __launch_bounds__(256) void layernorm_kernel(
    const float* __restrict__ enc, const float* __restrict__ x,
    const float* __restrict__ gamma, const float* __restrict__ beta,
    float* __restrict__ out) {
    __shared__ float zbuf[LL];
    __shared__ float red[256];
    int row = blockIdx.x;
    int tid = threadIdx.x;
    const float* e = enc + (size_t)row * LL;
    const float* xx = x + (size_t)row * LL;
    float* op = out + (size_t)row * LL;

    float s = 0.f;
    for (int t = tid; t < LL; t += 256) {
        float z = e[t] + xx[t];
        zbuf[t] = z;
        s += z;
    }
    red[tid] = s;
    __syncthreads();
    #pragma unroll
    for (int o = 128; o > 0; o >>= 1) {
        if (tid < o) red[tid] += red[tid + o];
        __syncthreads();
    }
    float mean = red[0] * (1.f / LL);
    __syncthreads();

    float v = 0.f;
    for (int t = tid; t < LL; t += 256) {
        float d = zbuf[t] - mean;
        v += d * d;
    }
    red[tid] = v;
    __syncthreads();
    #pragma unroll
    for (int o = 128; o > 0; o >>= 1) {
        if (tid < o) red[tid] += red[tid + o];
        __syncthreads();
    }
    float rstd = rsqrtf(red[0] * (1.f / LL) + 1e-12f);

    for (int t = tid; t < LL; t += 256)
        op[t] = (zbuf[t] - mean) * rstd * gamma[t] + beta[t];
}

// ---------------------------------------------------------------------------
// Launch
// ---------------------------------------------------------------------------
extern "C" void kernel_launch(void* const* d_in, const int* in_sizes, int n_in,
                              void* d_out, int out_size) {
    const float* x = (const float*)d_in[0];
    const float* W_ih = (const float*)d_in[1];
    const float* W_hh = (const float*)d_in[2];
    const float* b_ih = (const float*)d_in[3];
    const float* b_hh = (const float*)d_in[4];
    const float* gamma = (const float*)d_in[5];
    const float* beta = (const float*)d_in[6];
    float* out = (float*)d_out;

    float *pu, *pp, *px3, *pa3;
    __half *pwih, *pwhh;
    cudaGetSymbolAddress((void**)&pu, g_u);
    cudaGetSymbolAddress((void**)&pp, g_p);
    cudaGetSymbolAddress((void**)&px3, g_x3);
    cudaGetSymbolAddress((void**)&pa3, g_a3);
    cudaGetSymbolAddress((void**)&pwih, g_wih);
    cudaGetSymbolAddress((void**)&pwhh, g_whh);
    __half* hx3 = (__half*)px3;   // X3 input, later B2 split
    __half* ha3 = (__half*)pa3;   // relu(U) split; later enc (fp32)

    cudaFuncSetAttribute(gemm_hmma<true, true>, cudaFuncAttributeMaxDynamicSharedMemorySize, SM_TOTAL);
    cudaFuncSetAttribute(gemm_hmma<false, false>, cudaFuncAttributeMaxDynamicSharedMemorySize, SM_TOTAL);

    dim3 tgrid(LL / 32, DD / 32, BZ), tblk(32, 8);
    dim3 ggrid(DD / 128, MM / 128);  // (6, 128)
    const int ew_blocks = (MM * DD / 4 + 255) / 256;

    // W casts
    conv_w_kernel<<<(DD * DD + 255) / 256, 256>>>(W_ih, pwih);
    conv_w_kernel<<<(DD * DD + 255) / 256, 256>>>(W_hh, pwhh);
    // X3 = split(transpose(x))
    conv_x_kernel<<<tgrid, tblk>>>(x, hx3);
    // U = X @ W_ih^T + b_ih + b_hh ; fused: A3relu = split(relu(U))
    gemm_hmma<true, true><<<ggrid, 256, SM_TOTAL>>>(hx3, pwih, b_ih, b_hh, pu, ha3);
    // P = relu(U) @ W_hh^T
    gemm_hmma<false, false><<<ggrid, 256, SM_TOTAL>>>(ha3, pwhh, nullptr, nullptr, pp, nullptr);
    // B2split = split(relu(U + shift(P)))  -> g_x3 (X3 dead after GEMM1)
    conv_shift_kernel<<<ew_blocks, 256>>>(pu, pp, hx3);
    // Q = B2 @ W_hh^T
    gemm_hmma<false, false><<<ggrid, 256, SM_TOTAL>>>(hx3, pwhh, nullptr, nullptr, pp, nullptr);
    // enc = transpose(relu(U + shift(Q)))  -> g_a3 as fp32
    c3_transpose_kernel<<<tgrid, tblk>>>(pu, pp, pa3);
    // out = LayerNorm_L(enc + x)
    layernorm_kernel<<<BZ * DD, 256>>>(pa3, x, gamma, beta, out);
}

// round 13
// speedup vs baseline: 2.3683x; 1.5331x over previous
#include <cuda_runtime.h>
#include <cuda_fp16.h>
#include <cstdint>

#define BZ 4
#define DD 768
#define LL 4096
#define MM (BZ * LL)   // 16384
#define BKC 64
#define NKC 12         // 768 / 64 k-chunks
#define AS_STRIDE 72   // padded halfs per smem row (144B, ldmatrix conflict-free)
#define STAGE_BYTES (128 * AS_STRIDE * 2)  // 18432
#define NSTAGE 3
#define SM_TOTAL (NSTAGE * 2 * STAGE_BYTES)  // 110592

// Scratch (static device memory; no runtime alloc)
__device__ __align__(16) float g_u[MM * DD];        // U (fp32)
__device__ __align__(16) float g_p[MM * DD];        // P / Q (fp32)
__device__ __align__(16) __half g_xa[MM * DD];      // Xh input, later B2h
__device__ __align__(16) float g_a[MM * DD];        // relu(U) half OR enc fp32
__device__ __align__(16) __half g_wih[DD * DD];     // W_ih fp16
__device__ __align__(16) __half g_whh[DD * DD];     // W_hh fp16

// ---------------------------------------------------------------------------
// PTX helpers (plain sm_80-era ISA: valid on virtual compute_103)
// ---------------------------------------------------------------------------
__device__ __forceinline__ uint32_t smem_u32(const void* p) {
    uint32_t a;
    asm("{ .reg .u64 t; cvta.to.shared.u64 t, %1; cvt.u32.u64 %0, t; }" : "=r"(a) : "l"(p));
    return a;
}
__device__ __forceinline__ void cp_async16(uint32_t saddr, const void* gaddr) {
    asm volatile("cp.async.cg.shared.global [%0], [%1], 16;" :: "r"(saddr), "l"(gaddr));
}
__device__ __forceinline__ void cp_commit() {
    asm volatile("cp.async.commit_group;");
}
__device__ __forceinline__ void cp_wait1() {
    asm volatile("cp.async.wait_group 1;");
}
__device__ __forceinline__ void ldm_x4(uint32_t& r0, uint32_t& r1, uint32_t& r2, uint32_t& r3,
                                       uint32_t addr) {
    asm volatile("ldmatrix.sync.aligned.m8n8.x4.shared.b16 {%0,%1,%2,%3}, [%4];"
                 : "=r"(r0), "=r"(r1), "=r"(r2), "=r"(r3) : "r"(addr));
}
__device__ __forceinline__ void mma16816(float* c, const uint32_t* a, const uint32_t* b) {
    asm volatile(
        "mma.sync.aligned.m16n8k16.row.col.f32.f16.f16.f32 "
        "{%0,%1,%2,%3}, {%4,%5,%6,%7}, {%8,%9}, {%0,%1,%2,%3};"
        : "+f"(c[0]), "+f"(c[1]), "+f"(c[2]), "+f"(c[3])
        : "r"(a[0]), "r"(a[1]), "r"(a[2]), "r"(a[3]), "r"(b[0]), "r"(b[1]));
}

// ---------------------------------------------------------------------------
// HMMA GEMM: C[M,768] = Ah[M,768] @ Wh[768,768]^T (+ bias1+bias2)
// BM=BN=128, BK=64, 8 warps (4x2), warp tile 32x64, 3-stage cp.async.
// If HALF_OUT: also writes Aout = half(relu(C)).
// ---------------------------------------------------------------------------
template <bool ADD_BIAS, bool HALF_OUT>
__global__ __launch_bounds__(256, 2) void gemm_hmma(
    const __half* __restrict__ A, const __half* __restrict__ Bh,
    const float* __restrict__ bias1, const float* __restrict__ bias2,
    float* __restrict__ C, __half* __restrict__ Aout) {
    extern __shared__ __align__(16) unsigned char smem[];
    const uint32_t sa_base = smem_u32(smem);                       // A stages
    const uint32_t sb_base = sa_base + NSTAGE * STAGE_BYTES;       // B stages

    const int tid = threadIdx.x;
    const int wid = tid >> 5, lane = tid & 31;
    const int m0 = blockIdx.y * 128, n0 = blockIdx.x * 128;
    const int warp_m = (wid >> 1) * 32;   // 0,32,64,96
    const int warp_n = (wid & 1) * 64;    // 0,64

    // cp.async coords: 1024 16B-chunks per operand per stage; 4 per thread.
    const int cr = tid >> 3;          // row base 0..31 (+q*32)
    const int cc = (tid & 7) * 8;     // half col 0..56

    float acc[2][8][4] = {};

    // ldmatrix per-lane address components
    const int a_row = warp_m + (lane & 7) + ((lane >> 3) & 1) * 8;  // + mt*16
    const int a_colh = (lane >> 4) * 8;                              // + ks*16
    const int b_row = warp_n + (lane & 7) + (lane >> 4) * 8;         // + j*16
    const int b_colh = ((lane >> 3) & 1) * 8;                        // + ks*16

    auto load_stage = [&](int chunk, int stage) {
        const int kb = chunk * BKC;
        const uint32_t sa = sa_base + stage * STAGE_BYTES;
        const uint32_t sb = sb_base + stage * STAGE_BYTES;
        #pragma unroll
        for (int q = 0; q < 4; ++q) {
            const int r = cr + q * 32;
            cp_async16(sa + (r * AS_STRIDE + cc) * 2, A + (size_t)(m0 + r) * DD + kb + cc);
            cp_async16(sb + (r * AS_STRIDE + cc) * 2, Bh + (size_t)(n0 + r) * DD + kb + cc);
        }
    };

    // prologue: stages 0,1
    load_stage(0, 0); cp_commit();
    load_stage(1, 1); cp_commit();

    for (int i = 0; i < NKC; ++i) {
        cp_wait1();
        __syncthreads();
        if (i + 2 < NKC) load_stage(i + 2, (i + 2) % NSTAGE);
        cp_commit();

        const int st = i % NSTAGE;
        const uint32_t a_st = sa_base + st * STAGE_BYTES;
        const uint32_t b_st = sb_base + st * STAGE_BYTES;

        #pragma unroll
        for (int ks = 0; ks < 4; ++ks) {
            uint32_t af[2][4], bf[8][2];
            #pragma unroll
            for (int mt = 0; mt < 2; ++mt)
                ldm_x4(af[mt][0], af[mt][1], af[mt][2], af[mt][3],
                       a_st + ((a_row + mt * 16) * AS_STRIDE + a_colh + ks * 16) * 2);
            #pragma unroll
            for (int j = 0; j < 4; ++j)
                ldm_x4(bf[2 * j][0], bf[2 * j][1], bf[2 * j + 1][0], bf[2 * j + 1][1],
                       b_st + ((b_row + j * 16) * AS_STRIDE + b_colh + ks * 16) * 2);
            #pragma unroll
            for (int mt = 0; mt < 2; ++mt)
                #pragma unroll
                for (int nt = 0; nt < 8; ++nt)
                    mma16816(acc[mt][nt], af[mt], bf[nt]);
        }
    }

    // epilogue
    #pragma unroll
    for (int mt = 0; mt < 2; ++mt) {
        #pragma unroll
        for (int h = 0; h < 2; ++h) {
            const int row = m0 + warp_m + mt * 16 + (lane >> 2) + h * 8;
            const int colb = n0 + warp_n + (lane & 3) * 2;
            float* cp = C + (size_t)row * DD + colb;
            #pragma unroll
            for (int nt = 0; nt < 8; ++nt) {
                float2 v;
                v.x = acc[mt][nt][h * 2 + 0];
                v.y = acc[mt][nt][h * 2 + 1];
                if (ADD_BIAS) {
                    const int n = colb + nt * 8;
                    v.x += bias1[n + 0] + bias2[n + 0];
                    v.y += bias1[n + 1] + bias2[n + 1];
                }
                *(float2*)(cp + nt * 8) = v;
                if (HALF_OUT) {
                    __half hh[2];
                    hh[0] = __float2half_rn(fmaxf(v.x, 0.f));
                    hh[1] = __float2half_rn(fmaxf(v.y, 0.f));
                    *(uint32_t*)(Aout + (size_t)row * DD + colb + nt * 8) = *(const uint32_t*)hh;
                }
            }
        }
    }
}

// ---------------------------------------------------------------------------
// Elementwise / prep kernels
// ---------------------------------------------------------------------------
// W [768,768] fp32 -> half
__global__ void conv_w_kernel(const float* __restrict__ W, __half* __restrict__ Wh) {
    int idx = blockIdx.x * 256 + threadIdx.x;
    if (idx >= DD * DD) return;
    Wh[idx] = __float2half_rn(W[idx]);
}

// x [B,D,L] fp32 -> Xh [B*L, 768] half (transpose + cast)
__global__ void conv_x_kernel(const float* __restrict__ x, __half* __restrict__ Xh) {
    __shared__ float tile[32][33];
    int b = blockIdx.z, t0 = blockIdx.x * 32, d0 = blockIdx.y * 32;
    int tx = threadIdx.x;
    #pragma unroll
    for (int i = threadIdx.y; i < 32; i += 8)
        tile[tx][i] = x[(size_t)(b * DD + d0 + i) * LL + t0 + tx];
    __syncthreads();
    #pragma unroll
    for (int i = threadIdx.y; i < 32; i += 8)
        Xh[(size_t)(b * LL + t0 + i) * DD + d0 + tx] = __float2half_rn(tile[i][tx]);
}

// Ah = half(relu(U + shift(P)))
__global__ void conv_shift_kernel(const float* __restrict__ U, const float* __restrict__ P,
                                  __half* __restrict__ Ah) {
    int idx = blockIdx.x * 256 + threadIdx.x;
    int e = idx * 4;
    if (e >= MM * DD) return;
    int r = e / DD;
    int t = r & (LL - 1);
    float4 u = *(const float4*)(U + e);
    float4 p = make_float4(0.f, 0.f, 0.f, 0.f);
    if (t > 0) p = *(const float4*)(P + e - DD);
    __half h[4];
    h[0] = __float2half_rn(fmaxf(u.x + p.x, 0.f));
    h[1] = __float2half_rn(fmaxf(u.y + p.y, 0.f));
    h[2] = __float2half_rn(fmaxf(u.z + p.z, 0.f));
    h[3] = __float2half_rn(fmaxf(u.w + p.w, 0.f));
    *(uint2*)(Ah + e) = *(const uint2*)h;
}

// enc = transpose(relu(U + shift(Q))) -> [B, D, L] fp32
__global__ void c3_transpose_kernel(const float* __restrict__ U, const float* __restrict__ Q,
                                    float* __restrict__ enc) {
    __shared__ float tile[32][33];
    int b = blockIdx.z, t0 = blockIdx.x * 32, d0 = blockIdx.y * 32;
    int tx = threadIdx.x;
    #pragma unroll
    for (int i = threadIdx.y; i < 32; i += 8) {
        int t = t0 + i;
        int r = b * LL + t;
        float u = U[(size_t)r * DD + d0 + tx];
        float q = (t > 0) ? Q[(size_t)(r - 1) * DD + d0 + tx] : 0.f;
        tile[i][tx] = fmaxf(u + q, 0.f);
    }
    __syncthreads();
    #pragma unroll
    for (int i = threadIdx.y; i < 32; i += 8)
        enc[(size_t)(b * DD + d0 + i) * LL + t0 + tx] = tile[tx][i];
}

// LayerNorm over L per (b,d) row
__global__ __launch_bounds__(256) void layernorm_kernel(
    const float* __restrict__ enc, const float* __restrict__ x,
    const float* __restrict__ gamma, const float* __restrict__ beta,
    float* __restrict__ out) {
    __shared__ float zbuf[LL];
    __shared__ float red[256];
    int row = blockIdx.x;
    int tid = threadIdx.x;
    const float* e = enc + (size_t)row * LL;
    const float* xx = x + (size_t)row * LL;
    float* op = out + (size_t)row * LL;

    float s = 0.f;
    for (int t = tid; t < LL; t += 256) {
        float z = e[t] + xx[t];
        zbuf[t] = z;
        s += z;
    }
    red[tid] = s;
    __syncthreads();
    #pragma unroll
    for (int o = 128; o > 0; o >>= 1) {
        if (tid < o) red[tid] += red[tid + o];
        __syncthreads();
    }
    float mean = red[0] * (1.f / LL);
    __syncthreads();

    float v = 0.f;
    for (int t = tid; t < LL; t += 256) {
        float d = zbuf[t] - mean;
        v += d * d;
    }
    red[tid] = v;
    __syncthreads();
    #pragma unroll
    for (int o = 128; o > 0; o >>= 1) {
        if (tid < o) red[tid] += red[tid + o];
        __syncthreads();
    }
    float rstd = rsqrtf(red[0] * (1.f / LL) + 1e-12f);

    for (int t = tid; t < LL; t += 256)
        op[t] = (zbuf[t] - mean) * rstd * gamma[t] + beta[t];
}

// ---------------------------------------------------------------------------
// Launch
// ---------------------------------------------------------------------------
extern "C" void kernel_launch(void* const* d_in, const int* in_sizes, int n_in,
                              void* d_out, int out_size) {
    const float* x = (const float*)d_in[0];
    const float* W_ih = (const float*)d_in[1];
    const float* W_hh = (const float*)d_in[2];
    const float* b_ih = (const float*)d_in[3];
    const float* b_hh = (const float*)d_in[4];
    const float* gamma = (const float*)d_in[5];
    const float* beta = (const float*)d_in[6];
    float* out = (float*)d_out;

    float *pu, *pp, *pa;
    __half *pxa, *pwih, *pwhh;
    cudaGetSymbolAddress((void**)&pu, g_u);
    cudaGetSymbolAddress((void**)&pp, g_p);
    cudaGetSymbolAddress((void**)&pxa, g_xa);
    cudaGetSymbolAddress((void**)&pa, g_a);
    cudaGetSymbolAddress((void**)&pwih, g_wih);
    cudaGetSymbolAddress((void**)&pwhh, g_whh);
    __half* ha = (__half*)pa;   // relu(U) half; later enc fp32

    cudaFuncSetAttribute(gemm_hmma<true, true>, cudaFuncAttributeMaxDynamicSharedMemorySize, SM_TOTAL);
    cudaFuncSetAttribute(gemm_hmma<false, false>, cudaFuncAttributeMaxDynamicSharedMemorySize, SM_TOTAL);

    dim3 tgrid(LL / 32, DD / 32, BZ), tblk(32, 8);
    dim3 ggrid(DD / 128, MM / 128);  // (6, 128)
    const int ew_blocks = (MM * DD / 4 + 255) / 256;

    // W casts
    conv_w_kernel<<<(DD * DD + 255) / 256, 256>>>(W_ih, pwih);
    conv_w_kernel<<<(DD * DD + 255) / 256, 256>>>(W_hh, pwhh);
    // Xh = half(transpose(x))
    conv_x_kernel<<<tgrid, tblk>>>(x, pxa);
    // U = X @ W_ih^T + b_ih + b_hh ; fused: Arelu = half(relu(U))
    gemm_hmma<true, true><<<ggrid, 256, SM_TOTAL>>>(pxa, pwih, b_ih, b_hh, pu, ha);
    // P = relu(U) @ W_hh^T
    gemm_hmma<false, false><<<ggrid, 256, SM_TOTAL>>>(ha, pwhh, nullptr, nullptr, pp, nullptr);
    // B2h = half(relu(U + shift(P)))  -> g_xa (X dead after GEMM1)
    conv_shift_kernel<<<ew_blocks, 256>>>(pu, pp, pxa);
    // Q = B2 @ W_hh^T
    gemm_hmma<false, false><<<ggrid, 256, SM_TOTAL>>>(pxa, pwhh, nullptr, nullptr, pp, nullptr);
    // enc = transpose(relu(U + shift(Q)))  -> g_a as fp32
    c3_transpose_kernel<<<tgrid, tblk>>>(pu, pp, pa);
    // out = LayerNorm_L(enc + x)
    layernorm_kernel<<<BZ * DD, 256>>>(pa, x, gamma, beta, out);
}

// round 14
// speedup vs baseline: 2.6874x; 1.1348x over previous
#include <cuda_runtime.h>
#include <cuda_fp16.h>
#include <cstdint>

#define BZ 4
#define DD 768
#define LL 4096
#define MM (BZ * LL)   // 16384
#define BKC 64
#define NKC 12         // 768 / 64 k-chunks
#define AS_STRIDE 72   // padded halfs per smem row (144B, ldmatrix conflict-free)
#define STAGE_BYTES (128 * AS_STRIDE * 2)  // 18432
#define NSTAGE 3
#define SM_TOTAL (NSTAGE * 2 * STAGE_BYTES)  // 110592

// Scratch (static device memory; no runtime alloc)
__device__ __align__(16) __half g_u[MM * DD];       // U (fp16)
__device__ __align__(16) __half g_p[MM * DD];       // P / Q (fp16)
__device__ __align__(16) __half g_xa[MM * DD];      // Xh input, later B2h
__device__ __align__(16) float g_a[MM * DD];        // relu(U) half (aliased) OR enc fp32
__device__ __align__(16) __half g_wih[DD * DD];     // W_ih fp16
__device__ __align__(16) __half g_whh[DD * DD];     // W_hh fp16

// ---------------------------------------------------------------------------
// PTX helpers (plain sm_80-era ISA: valid on virtual compute_103)
// ---------------------------------------------------------------------------
__device__ __forceinline__ uint32_t smem_u32(const void* p) {
    uint32_t a;
    asm("{ .reg .u64 t; cvta.to.shared.u64 t, %1; cvt.u32.u64 %0, t; }" : "=r"(a) : "l"(p));
    return a;
}
__device__ __forceinline__ void cp_async16(uint32_t saddr, const void* gaddr) {
    asm volatile("cp.async.cg.shared.global [%0], [%1], 16;" :: "r"(saddr), "l"(gaddr));
}
__device__ __forceinline__ void cp_commit() {
    asm volatile("cp.async.commit_group;");
}
__device__ __forceinline__ void cp_wait1() {
    asm volatile("cp.async.wait_group 1;");
}
__device__ __forceinline__ void ldm_x4(uint32_t& r0, uint32_t& r1, uint32_t& r2, uint32_t& r3,
                                       uint32_t addr) {
    asm volatile("ldmatrix.sync.aligned.m8n8.x4.shared.b16 {%0,%1,%2,%3}, [%4];"
                 : "=r"(r0), "=r"(r1), "=r"(r2), "=r"(r3) : "r"(addr));
}
__device__ __forceinline__ void mma16816(float* c, const uint32_t* a, const uint32_t* b) {
    asm volatile(
        "mma.sync.aligned.m16n8k16.row.col.f32.f16.f16.f32 "
        "{%0,%1,%2,%3}, {%4,%5,%6,%7}, {%8,%9}, {%0,%1,%2,%3};"
        : "+f"(c[0]), "+f"(c[1]), "+f"(c[2]), "+f"(c[3])
        : "r"(a[0]), "r"(a[1]), "r"(a[2]), "r"(a[3]), "r"(b[0]), "r"(b[1]));
}

// ---------------------------------------------------------------------------
// HMMA GEMM: C[M,768] (fp16) = Ah[M,768] @ Wh[768,768]^T (+ bias1+bias2)
// BM=BN=128, BK=64, 8 warps (4x2), warp tile 32x64, 3-stage cp.async.
// If RELU_OUT: also writes Aout = half(relu(C)).
// ---------------------------------------------------------------------------
template <bool ADD_BIAS, bool RELU_OUT>
__global__ __launch_bounds__(256, 2) void gemm_hmma(
    const __half* __restrict__ A, const __half* __restrict__ Bh,
    const float* __restrict__ bias1, const float* __restrict__ bias2,
    __half* __restrict__ C, __half* __restrict__ Aout) {
    extern __shared__ __align__(16) unsigned char smem[];
    const uint32_t sa_base = smem_u32(smem);                       // A stages
    const uint32_t sb_base = sa_base + NSTAGE * STAGE_BYTES;       // B stages

    const int tid = threadIdx.x;
    const int wid = tid >> 5, lane = tid & 31;
    const int m0 = blockIdx.y * 128, n0 = blockIdx.x * 128;
    const int warp_m = (wid >> 1) * 32;   // 0,32,64,96
    const int warp_n = (wid & 1) * 64;    // 0,64

    // cp.async coords: 1024 16B-chunks per operand per stage; 4 per thread.
    const int cr = tid >> 3;          // row base 0..31 (+q*32)
    const int cc = (tid & 7) * 8;     // half col 0..56

    float acc[2][8][4] = {};

    // ldmatrix per-lane address components
    const int a_row = warp_m + (lane & 7) + ((lane >> 3) & 1) * 8;  // + mt*16
    const int a_colh = (lane >> 4) * 8;                              // + ks*16
    const int b_row = warp_n + (lane & 7) + (lane >> 4) * 8;         // + j*16
    const int b_colh = ((lane >> 3) & 1) * 8;                        // + ks*16

    auto load_stage = [&](int chunk, int stage) {
        const int kb = chunk * BKC;
        const uint32_t sa = sa_base + stage * STAGE_BYTES;
        const uint32_t sb = sb_base + stage * STAGE_BYTES;
        #pragma unroll
        for (int q = 0; q < 4; ++q) {
            const int r = cr + q * 32;
            cp_async16(sa + (r * AS_STRIDE + cc) * 2, A + (size_t)(m0 + r) * DD + kb + cc);
            cp_async16(sb + (r * AS_STRIDE + cc) * 2, Bh + (size_t)(n0 + r) * DD + kb + cc);
        }
    };

    // prologue: stages 0,1
    load_stage(0, 0); cp_commit();
    load_stage(1, 1); cp_commit();

    for (int i = 0; i < NKC; ++i) {
        cp_wait1();
        __syncthreads();
        if (i + 2 < NKC) load_stage(i + 2, (i + 2) % NSTAGE);
        cp_commit();

        const int st = i % NSTAGE;
        const uint32_t a_st = sa_base + st * STAGE_BYTES;
        const uint32_t b_st = sb_base + st * STAGE_BYTES;

        #pragma unroll
        for (int ks = 0; ks < 4; ++ks) {
            uint32_t af[2][4], bf[8][2];
            #pragma unroll
            for (int mt = 0; mt < 2; ++mt)
                ldm_x4(af[mt][0], af[mt][1], af[mt][2], af[mt][3],
                       a_st + ((a_row + mt * 16) * AS_STRIDE + a_colh + ks * 16) * 2);
            #pragma unroll
            for (int j = 0; j < 4; ++j)
                ldm_x4(bf[2 * j][0], bf[2 * j][1], bf[2 * j + 1][0], bf[2 * j + 1][1],
                       b_st + ((b_row + j * 16) * AS_STRIDE + b_colh + ks * 16) * 2);
            #pragma unroll
            for (int mt = 0; mt < 2; ++mt)
                #pragma unroll
                for (int nt = 0; nt < 8; ++nt)
                    mma16816(acc[mt][nt], af[mt], bf[nt]);
        }
    }

    // epilogue: fp32 acc (+bias) -> fp16 store
    #pragma unroll
    for (int mt = 0; mt < 2; ++mt) {
        #pragma unroll
        for (int h = 0; h < 2; ++h) {
            const int row = m0 + warp_m + mt * 16 + (lane >> 2) + h * 8;
            const int colb = n0 + warp_n + (lane & 3) * 2;
            __half* cp = C + (size_t)row * DD + colb;
            #pragma unroll
            for (int nt = 0; nt < 8; ++nt) {
                float vx = acc[mt][nt][h * 2 + 0];
                float vy = acc[mt][nt][h * 2 + 1];
                if (ADD_BIAS) {
                    const int n = colb + nt * 8;
                    vx += bias1[n + 0] + bias2[n + 0];
                    vy += bias1[n + 1] + bias2[n + 1];
                }
                __half hh[2];
                hh[0] = __float2half_rn(vx);
                hh[1] = __float2half_rn(vy);
                *(uint32_t*)(cp + nt * 8) = *(const uint32_t*)hh;
                if (RELU_OUT) {
                    __half rr[2];
                    rr[0] = __float2half_rn(fmaxf(vx, 0.f));
                    rr[1] = __float2half_rn(fmaxf(vy, 0.f));
                    *(uint32_t*)(Aout + (size_t)row * DD + colb + nt * 8) = *(const uint32_t*)rr;
                }
            }
        }
    }
}

// ---------------------------------------------------------------------------
// Elementwise / prep kernels
// ---------------------------------------------------------------------------
// W [768,768] fp32 -> half
__global__ void conv_w_kernel(const float* __restrict__ W, __half* __restrict__ Wh) {
    int idx = blockIdx.x * 256 + threadIdx.x;
    if (idx >= DD * DD) return;
    Wh[idx] = __float2half_rn(W[idx]);
}

// x [B,D,L] fp32 -> Xh [B*L, 768] half (transpose + cast)
__global__ void conv_x_kernel(const float* __restrict__ x, __half* __restrict__ Xh) {
    __shared__ float tile[32][33];
    int b = blockIdx.z, t0 = blockIdx.x * 32, d0 = blockIdx.y * 32;
    int tx = threadIdx.x;
    #pragma unroll
    for (int i = threadIdx.y; i < 32; i += 8)
        tile[tx][i] = x[(size_t)(b * DD + d0 + i) * LL + t0 + tx];
    __syncthreads();
    #pragma unroll
    for (int i = threadIdx.y; i < 32; i += 8)
        Xh[(size_t)(b * LL + t0 + i) * DD + d0 + tx] = __float2half_rn(tile[i][tx]);
}

// B2h = half(relu(U + shift(P)))   (all fp16, 8 halfs per thread)
__global__ void conv_shift_kernel(const __half* __restrict__ U, const __half* __restrict__ P,
                                  __half* __restrict__ Ah) {
    int idx = blockIdx.x * 256 + threadIdx.x;
    int e = idx * 8;
    if (e >= MM * DD) return;
    int r = e / DD;
    int t = r & (LL - 1);
    uint4 uu = *(const uint4*)(U + e);
    uint4 pp = make_uint4(0u, 0u, 0u, 0u);
    if (t > 0) pp = *(const uint4*)(P + e - DD);
    const __half2 zero2 = __float2half2_rn(0.f);
    __half2* u2 = (__half2*)&uu;
    __half2* p2 = (__half2*)&pp;
    uint4 oo;
    __half2* o2 = (__half2*)&oo;
    #pragma unroll
    for (int j = 0; j < 4; ++j)
        o2[j] = __hmax2(__hadd2(u2[j], p2[j]), zero2);
    *(uint4*)(Ah + e) = oo;
}

// enc = transpose(relu(U + shift(Q))) -> [B, D, L] fp32
__global__ void c3_transpose_kernel(const __half* __restrict__ U, const __half* __restrict__ Q,
                                    float* __restrict__ enc) {
    __shared__ float tile[32][33];
    int b = blockIdx.z, t0 = blockIdx.x * 32, d0 = blockIdx.y * 32;
    int tx = threadIdx.x;
    #pragma unroll
    for (int i = threadIdx.y; i < 32; i += 8) {
        int t = t0 + i;
        int r = b * LL + t;
        float u = __half2float(U[(size_t)r * DD + d0 + tx]);
        float q = (t > 0) ? __half2float(Q[(size_t)(r - 1) * DD + d0 + tx]) : 0.f;
        tile[i][tx] = fmaxf(u + q, 0.f);
    }
    __syncthreads();
    #pragma unroll
    for (int i = threadIdx.y; i < 32; i += 8)
        enc[(size_t)(b * DD + d0 + i) * LL + t0 + tx] = tile[tx][i];
}

// LayerNorm over L per (b,d) row (float4 vectorized)
__global__ __launch_bounds__(256) void layernorm_kernel(
    const float* __restrict__ enc, const float* __restrict__ x,
    const float* __restrict__ gamma, const float* __restrict__ beta,
    float* __restrict__ out) {
    __shared__ __align__(16) float zbuf[LL];
    __shared__ float red[256];
    int row = blockIdx.x;
    int tid = threadIdx.x;
    const float4* e4 = (const float4*)(enc + (size_t)row * LL);
    const float4* x4 = (const float4*)(x + (size_t)row * LL);
    float4* o4 = (float4*)(out + (size_t)row * LL);
    const float4* g4 = (const float4*)gamma;
    const float4* be4 = (const float4*)beta;

    float s = 0.f;
    #pragma unroll
    for (int i = tid; i < LL / 4; i += 256) {
        float4 e = e4[i], xx = x4[i];
        float4 z;
        z.x = e.x + xx.x; z.y = e.y + xx.y; z.z = e.z + xx.z; z.w = e.w + xx.w;
        ((float4*)zbuf)[i] = z;
        s += z.x + z.y + z.z + z.w;
    }
    red[tid] = s;
    __syncthreads();
    #pragma unroll
    for (int o = 128; o > 0; o >>= 1) {
        if (tid < o) red[tid] += red[tid + o];
        __syncthreads();
    }
    float mean = red[0] * (1.f / LL);
    __syncthreads();

    float v = 0.f;
    #pragma unroll
    for (int i = tid; i < LL / 4; i += 256) {
        float4 z = ((float4*)zbuf)[i];
        float dx = z.x - mean, dy = z.y - mean, dz = z.z - mean, dw = z.w - mean;
        v += dx * dx + dy * dy + dz * dz + dw * dw;
    }
    red[tid] = v;
    __syncthreads();
    #pragma unroll
    for (int o = 128; o > 0; o >>= 1) {
        if (tid < o) red[tid] += red[tid + o];
        __syncthreads();
    }
    float rstd = rsqrtf(red[0] * (1.f / LL) + 1e-12f);

    #pragma unroll
    for (int i = tid; i < LL / 4; i += 256) {
        float4 z = ((float4*)zbuf)[i];
        float4 g = g4[i], bb = be4[i];
        float4 o;
        o.x = (z.x - mean) * rstd * g.x + bb.x;
        o.y = (z.y - mean) * rstd * g.y + bb.y;
        o.z = (z.z - mean) * rstd * g.z + bb.z;
        o.w = (z.w - mean) * rstd * g.w + bb.w;
        o4[i] = o;
    }
}

// ---------------------------------------------------------------------------
// Launch
// ---------------------------------------------------------------------------
extern "C" void kernel_launch(void* const* d_in, const int* in_sizes, int n_in,
                              void* d_out, int out_size) {
    const float* x = (const float*)d_in[0];
    const float* W_ih = (const float*)d_in[1];
    const float* W_hh = (const float*)d_in[2];
    const float* b_ih = (const float*)d_in[3];
    const float* b_hh = (const float*)d_in[4];
    const float* gamma = (const float*)d_in[5];
    const float* beta = (const float*)d_in[6];
    float* out = (float*)d_out;

    __half *pu, *pp, *pxa, *pwih, *pwhh;
    float* pa;
    cudaGetSymbolAddress((void**)&pu, g_u);
    cudaGetSymbolAddress((void**)&pp, g_p);
    cudaGetSymbolAddress((void**)&pxa, g_xa);
    cudaGetSymbolAddress((void**)&pa, g_a);
    cudaGetSymbolAddress((void**)&pwih, g_wih);
    cudaGetSymbolAddress((void**)&pwhh, g_whh);
    __half* ha = (__half*)pa;   // relu(U) half; later enc fp32

    cudaFuncSetAttribute(gemm_hmma<true, true>, cudaFuncAttributeMaxDynamicSharedMemorySize, SM_TOTAL);
    cudaFuncSetAttribute(gemm_hmma<false, false>, cudaFuncAttributeMaxDynamicSharedMemorySize, SM_TOTAL);

    dim3 tgrid(LL / 32, DD / 32, BZ), tblk(32, 8);
    dim3 ggrid(DD / 128, MM / 128);  // (6, 128)
    const int ew_blocks = (MM * DD / 8 + 255) / 256;

    // W casts
    conv_w_kernel<<<(DD * DD + 255) / 256, 256>>>(W_ih, pwih);
    conv_w_kernel<<<(DD * DD + 255) / 256, 256>>>(W_hh, pwhh);
    // Xh = half(transpose(x))
    conv_x_kernel<<<tgrid, tblk>>>(x, pxa);
    // U = X @ W_ih^T + b_ih + b_hh (half) ; fused: Arelu = half(relu(U))
    gemm_hmma<true, true><<<ggrid, 256, SM_TOTAL>>>(pxa, pwih, b_ih, b_hh, pu, ha);
    // P = relu(U) @ W_hh^T (half)
    gemm_hmma<false, false><<<ggrid, 256, SM_TOTAL>>>(ha, pwhh, nullptr, nullptr, pp, nullptr);
    // B2h = half(relu(U + shift(P)))  -> g_xa (X dead after GEMM1)
    conv_shift_kernel<<<ew_blocks, 256>>>(pu, pp, pxa);
    // Q = B2 @ W_hh^T (half)
    gemm_hmma<false, false><<<ggrid, 256, SM_TOTAL>>>(pxa, pwhh, nullptr, nullptr, pp, nullptr);
    // enc = transpose(relu(U + shift(Q)))  -> g_a as fp32
    c3_transpose_kernel<<<tgrid, tblk>>>(pu, pp, pa);
    // out = LayerNorm_L(enc + x)
    layernorm_kernel<<<BZ * DD, 256>>>(pa, x, gamma, beta, out);
}